// round 2
// baseline (speedup 1.0000x reference)
#include <cuda_runtime.h>
#include <cstdint>

#define D 1024
#define B_TOK 16384
#define E_EXP 8
#define NSLOT (2 * B_TOK)

// ---------------- scratch: __device__ globals (no allocations allowed) ----------------
__device__ float  g_Wog[D * E_EXP];        // Wo @ Wg
__device__ float  g_Wvog[D * E_EXP];       // Wv @ (Wo @ Wg)
__device__ float  g_beff[E_EXP];           // bv@Wog + bo@Wg + bg
__device__ int    g_tok_e[2 * B_TOK];      // per-token top-2 expert ids
__device__ float  g_tok_w[2 * B_TOK];      // per-token renormalized weights
__device__ int    g_tok_slot[2 * B_TOK];   // per-token slot indices
__device__ int    g_counts[E_EXP];
__device__ int    g_offsets[E_EXP];
__device__ int    g_cursor[E_EXP];
__device__ double g_imp[E_EXP];
__device__ int    g_slot_tok[NSLOT];
__device__ float  g_slot_w[NSLOT];
__device__ float  g_h1[(size_t)NSLOT * D]; // expert hidden (silu output), 128 MB
__device__ float  g_h2[(size_t)NSLOT * D]; // expert output (scaled), 128 MB

// ---------------- zero the per-call accumulators ----------------
__global__ void k_zero() {
    int t = threadIdx.x;
    if (t < E_EXP) { g_counts[t] = 0; g_cursor[t] = 0; g_imp[t] = 0.0; }
}

// ---------------- out[r][e] = sum_k A[r*D+k] * Bm[k*8+e]  (D x 8 result) ----------------
// which==0: Bm = BmArg (Wg), out = g_Wog.   which==1: Bm = g_Wog, out = g_Wvog.
__global__ __launch_bounds__(256) void k_mat_small(const float* __restrict__ A,
                                                   const float* __restrict__ BmArg,
                                                   int which) {
    const float* Bm = (which == 0) ? BmArg : g_Wog;
    float* out = (which == 0) ? g_Wog : g_Wvog;
    int r = blockIdx.x;
    float acc[8];
#pragma unroll
    for (int e = 0; e < 8; e++) acc[e] = 0.f;
    for (int k = threadIdx.x; k < D; k += 256) {
        float a = A[(size_t)r * D + k];
        const float4* b4 = reinterpret_cast<const float4*>(Bm + (size_t)k * 8);
        float4 b0 = b4[0], b1 = b4[1];
        acc[0] += a * b0.x; acc[1] += a * b0.y; acc[2] += a * b0.z; acc[3] += a * b0.w;
        acc[4] += a * b1.x; acc[5] += a * b1.y; acc[6] += a * b1.z; acc[7] += a * b1.w;
    }
#pragma unroll
    for (int off = 16; off > 0; off >>= 1)
#pragma unroll
        for (int e = 0; e < 8; e++) acc[e] += __shfl_xor_sync(0xFFFFFFFFu, acc[e], off);
    __shared__ float sred[8][8];
    int warp = threadIdx.x >> 5, lane = threadIdx.x & 31;
    if (lane == 0)
#pragma unroll
        for (int e = 0; e < 8; e++) sred[warp][e] = acc[e];
    __syncthreads();
    if (threadIdx.x < 8) {
        float s = 0.f;
#pragma unroll
        for (int w = 0; w < 8; w++) s += sred[w][threadIdx.x];
        out[(size_t)r * 8 + threadIdx.x] = s;
    }
}

// ---------------- beff[e] = sum_k bv[k]*Wog[k,e] + sum_k bo[k]*Wg[k,e] + bg[e] ----------------
__global__ __launch_bounds__(256) void k_beff(const float* __restrict__ bv,
                                              const float* __restrict__ bo,
                                              const float* __restrict__ Wg,
                                              const float* __restrict__ bg) {
    float acc[8];
#pragma unroll
    for (int e = 0; e < 8; e++) acc[e] = 0.f;
    for (int k = threadIdx.x; k < D; k += 256) {
        float a = bv[k], b = bo[k];
        const float4* w4 = reinterpret_cast<const float4*>(g_Wog + (size_t)k * 8);
        const float4* g4 = reinterpret_cast<const float4*>(Wg + (size_t)k * 8);
        float4 w0 = w4[0], w1 = w4[1], g0 = g4[0], g1 = g4[1];
        acc[0] += a * w0.x + b * g0.x; acc[1] += a * w0.y + b * g0.y;
        acc[2] += a * w0.z + b * g0.z; acc[3] += a * w0.w + b * g0.w;
        acc[4] += a * w1.x + b * g1.x; acc[5] += a * w1.y + b * g1.y;
        acc[6] += a * w1.z + b * g1.z; acc[7] += a * w1.w + b * g1.w;
    }
#pragma unroll
    for (int off = 16; off > 0; off >>= 1)
#pragma unroll
        for (int e = 0; e < 8; e++) acc[e] += __shfl_xor_sync(0xFFFFFFFFu, acc[e], off);
    __shared__ float sred[8][8];
    int warp = threadIdx.x >> 5, lane = threadIdx.x & 31;
    if (lane == 0)
#pragma unroll
        for (int e = 0; e < 8; e++) sred[warp][e] = acc[e];
    __syncthreads();
    if (threadIdx.x < 8) {
        float s = 0.f;
#pragma unroll
        for (int w = 0; w < 8; w++) s += sred[w][threadIdx.x];
        g_beff[threadIdx.x] = s + bg[threadIdx.x];
    }
}

// ---------------- gating: logits, softmax, top-2, counts, importance ----------------
__global__ __launch_bounds__(256) void k_gate(const float* __restrict__ q,
                                              float* __restrict__ gate_out) {
    int warp = threadIdx.x >> 5, lane = threadIdx.x & 31;
    int b = blockIdx.x * 8 + warp;
    const float* qrow = q + (size_t)b * D;
    float acc[8];
#pragma unroll
    for (int e = 0; e < 8; e++) acc[e] = 0.f;
#pragma unroll 4
    for (int i = 0; i < 32; i++) {
        int k = i * 32 + lane;
        float qa = qrow[k];
        const float4* w4 = reinterpret_cast<const float4*>(g_Wvog + (size_t)k * 8);
        float4 w0 = w4[0], w1 = w4[1];
        acc[0] += qa * w0.x; acc[1] += qa * w0.y; acc[2] += qa * w0.z; acc[3] += qa * w0.w;
        acc[4] += qa * w1.x; acc[5] += qa * w1.y; acc[6] += qa * w1.z; acc[7] += qa * w1.w;
    }
#pragma unroll
    for (int off = 16; off > 0; off >>= 1)
#pragma unroll
        for (int e = 0; e < 8; e++) acc[e] += __shfl_xor_sync(0xFFFFFFFFu, acc[e], off);

    __shared__ double simp[8];
    if (threadIdx.x < 8) simp[threadIdx.x] = 0.0;
    __syncthreads();

    if (lane == 0) {
        float l[8];
#pragma unroll
        for (int e = 0; e < 8; e++) l[e] = acc[e] + g_beff[e];
        float m = l[0];
#pragma unroll
        for (int e = 1; e < 8; e++) m = fmaxf(m, l[e]);
        float ex[8], Z = 0.f;
#pragma unroll
        for (int e = 0; e < 8; e++) { ex[e] = expf(l[e] - m); Z += ex[e]; }
        float p[8];
        float invZ = 1.f / Z;
#pragma unroll
        for (int e = 0; e < 8; e++) p[e] = ex[e] * invZ;
#pragma unroll
        for (int e = 0; e < 8; e++) gate_out[(size_t)b * 8 + e] = p[e];

        int e1 = 0;
#pragma unroll
        for (int e = 1; e < 8; e++) if (p[e] > p[e1]) e1 = e;
        int e2 = (e1 == 0) ? 1 : 0;
#pragma unroll
        for (int e = 0; e < 8; e++) if (e != e1 && p[e] > p[e2]) e2 = e;
        // renormalize over top-2 (softmax of the PROBABILITIES, as in reference)
        float t = expf(p[e2] - p[e1]);      // p[e2] <= p[e1]
        float inv = 1.f / (1.f + t);
        g_tok_e[2 * b] = e1;  g_tok_e[2 * b + 1] = e2;
        g_tok_w[2 * b] = inv; g_tok_w[2 * b + 1] = t * inv;
        atomicAdd(&g_counts[e1], 1);
        atomicAdd(&g_counts[e2], 1);
#pragma unroll
        for (int e = 0; e < 8; e++) atomicAdd(&simp[e], (double)p[e]);
    }
    __syncthreads();
    if (threadIdx.x < 8) atomicAdd(&g_imp[threadIdx.x], simp[threadIdx.x]);
}

// ---------------- exclusive scan over 8 counts ----------------
__global__ void k_scan() {
    if (threadIdx.x == 0) {
        int o = 0;
#pragma unroll
        for (int e = 0; e < 8; e++) { g_offsets[e] = o; o += g_counts[e]; }
    }
}

// ---------------- scatter tokens into expert groups ----------------
__global__ __launch_bounds__(256) void k_scatter() {
    int b = blockIdx.x * 256 + threadIdx.x;
    if (b >= B_TOK) return;
#pragma unroll
    for (int j = 0; j < 2; j++) {
        int e = g_tok_e[2 * b + j];
        int s = g_offsets[e] + atomicAdd(&g_cursor[e], 1);
        g_slot_tok[s] = b;
        g_slot_w[s] = g_tok_w[2 * b + j];
        g_tok_slot[2 * b + j] = s;
    }
}

// ---------------- grouped fp32 GEMM: 128x128x8 tiles, 256 threads, 8x8 microtile ----------------
// MODE 1: g_h1[goff+r, :] = silu( x[slot_tok[goff+r], :] @ W1[e] + b1[e] )
// MODE 2: g_h2[goff+r, :] = slot_w[goff+r] * ( g_h1[goff+r, :] @ W2[e] + b2[e] )
template <int MODE>
__global__ __launch_bounds__(256) void k_gemm(const float* __restrict__ X,
                                              const float* __restrict__ Wbase,
                                              const float* __restrict__ bbase) {
    __shared__ float As[2][8][128];
    __shared__ float Bs[2][8][128];

    int e = blockIdx.z;
    int M = g_counts[e];
    int m0 = blockIdx.y * 128;
    if (m0 >= M) return;
    int n0 = blockIdx.x * 128;
    int goff = g_offsets[e];
    const float* Wp = Wbase + (size_t)e * D * D;
    const float* bp = bbase + (size_t)e * D;

    int tid = threadIdx.x;
    // A-load mapping: one float4 per thread per k-tile
    int ar = tid >> 1;            // row within tile 0..127
    int ak = (tid & 1) * 4;       // k offset 0 or 4
    int r = m0 + ar; if (r > M - 1) r = M - 1;
    const float* arow;
    if (MODE == 1) arow = X + (size_t)g_slot_tok[goff + r] * D;
    else           arow = g_h1 + (size_t)(goff + r) * D;
    // B-load mapping: one float4 per thread per k-tile
    int bk = tid >> 5;            // k row 0..7
    int bn = (tid & 31) * 4;      // col 0..124
    const float* bptr = Wp + (size_t)bk * D + n0 + bn;

    int tm = tid >> 4, tn = tid & 15;

    float acc[8][8];
#pragma unroll
    for (int i = 0; i < 8; i++)
#pragma unroll
        for (int j = 0; j < 8; j++) acc[i][j] = 0.f;

    float4 ag = *reinterpret_cast<const float4*>(arow + ak);
    float4 bgl = *reinterpret_cast<const float4*>(bptr);
    As[0][ak + 0][ar] = ag.x; As[0][ak + 1][ar] = ag.y;
    As[0][ak + 2][ar] = ag.z; As[0][ak + 3][ar] = ag.w;
    *reinterpret_cast<float4*>(&Bs[0][bk][bn]) = bgl;
    __syncthreads();

    const int NT = D / 8;
    for (int t = 0; t < NT; t++) {
        int cur = t & 1, nxt = cur ^ 1;
        if (t + 1 < NT) {
            ag  = *reinterpret_cast<const float4*>(arow + (t + 1) * 8 + ak);
            bgl = *reinterpret_cast<const float4*>(bptr + (size_t)(t + 1) * 8 * D);
        }
#pragma unroll
        for (int k = 0; k < 8; k++) {
            float4 a0 = *reinterpret_cast<const float4*>(&As[cur][k][tm * 8]);
            float4 a1 = *reinterpret_cast<const float4*>(&As[cur][k][tm * 8 + 4]);
            float4 b0 = *reinterpret_cast<const float4*>(&Bs[cur][k][tn * 8]);
            float4 b1 = *reinterpret_cast<const float4*>(&Bs[cur][k][tn * 8 + 4]);
            float a[8] = {a0.x, a0.y, a0.z, a0.w, a1.x, a1.y, a1.z, a1.w};
            float b[8] = {b0.x, b0.y, b0.z, b0.w, b1.x, b1.y, b1.z, b1.w};
#pragma unroll
            for (int i = 0; i < 8; i++)
#pragma unroll
                for (int j = 0; j < 8; j++) acc[i][j] += a[i] * b[j];
        }
        if (t + 1 < NT) {
            As[nxt][ak + 0][ar] = ag.x; As[nxt][ak + 1][ar] = ag.y;
            As[nxt][ak + 2][ar] = ag.z; As[nxt][ak + 3][ar] = ag.w;
            *reinterpret_cast<float4*>(&Bs[nxt][bk][bn]) = bgl;
        }
        __syncthreads();
    }

    // epilogue
    float bb[8];
    {
        const float4* bq = reinterpret_cast<const float4*>(bp + n0 + tn * 8);
        float4 q0 = bq[0], q1 = bq[1];
        bb[0] = q0.x; bb[1] = q0.y; bb[2] = q0.z; bb[3] = q0.w;
        bb[4] = q1.x; bb[5] = q1.y; bb[6] = q1.z; bb[7] = q1.w;
    }
    float* Cbase = (MODE == 1) ? g_h1 : g_h2;
#pragma unroll
    for (int i = 0; i < 8; i++) {
        int gr = m0 + tm * 8 + i;
        if (gr >= M) break;
        float v[8];
        float wr = 1.f;
        if (MODE == 2) wr = g_slot_w[goff + gr];
#pragma unroll
        for (int j = 0; j < 8; j++) {
            float z = acc[i][j] + bb[j];
            if (MODE == 1) v[j] = z / (1.f + expf(-z));   // silu
            else           v[j] = wr * z;
        }
        float* crow = Cbase + (size_t)(goff + gr) * D + n0 + tn * 8;
        *reinterpret_cast<float4*>(crow)     = make_float4(v[0], v[1], v[2], v[3]);
        *reinterpret_cast<float4*>(crow + 4) = make_float4(v[4], v[5], v[6], v[7]);
    }
}

// ---------------- combine: y[b] = h2[slot(b,0)] + h2[slot(b,1)] ----------------
__global__ __launch_bounds__(256) void k_combine(float* __restrict__ y) {
    int idx = blockIdx.x * 256 + threadIdx.x;   // over B*D/4 float4s
    int b = idx >> 8;                           // D/4 = 256 float4s per row
    int c = idx & 255;
    const float4* h2 = reinterpret_cast<const float4*>(g_h2);
    float4 u = h2[(size_t)g_tok_slot[2 * b] * 256 + c];
    float4 v = h2[(size_t)g_tok_slot[2 * b + 1] * 256 + c];
    reinterpret_cast<float4*>(y)[idx] = make_float4(u.x + v.x, u.y + v.y, u.z + v.z, u.w + v.w);
}

// ---------------- importance loss ----------------
__global__ void k_loss(float* __restrict__ out) {
    if (threadIdx.x == 0) {
        double s = 0.0;
#pragma unroll
        for (int e = 0; e < 8; e++) s += g_imp[e];
        double mean = s / 8.0;
        double var = 0.0;
#pragma unroll
        for (int e = 0; e < 8; e++) { double d = g_imp[e] - mean; var += d * d; }
        var /= 7.0;                                  // ddof=1
        out[0] = (float)(0.01 * var / (mean * mean)); // W_IMPORTANCE*(std/mean)^2
    }
}

extern "C" void kernel_launch(void* const* d_in, const int* in_sizes, int n_in,
                              void* d_out, int out_size) {
    const float* x  = (const float*)d_in[0];
    const float* q  = (const float*)d_in[1];
    const float* Wv = (const float*)d_in[2];
    const float* bv = (const float*)d_in[3];
    const float* Wo = (const float*)d_in[4];
    const float* bo = (const float*)d_in[5];
    const float* Wg = (const float*)d_in[6];
    const float* bg = (const float*)d_in[7];
    const float* W1 = (const float*)d_in[8];
    const float* b1 = (const float*)d_in[9];
    const float* W2 = (const float*)d_in[10];
    const float* b2 = (const float*)d_in[11];

    float* y        = (float*)d_out;
    float* gate_out = y + (size_t)B_TOK * D;
    float* loss_out = gate_out + (size_t)B_TOK * E_EXP;

    k_zero<<<1, 32>>>();
    k_mat_small<<<D, 256>>>(Wo, Wg, 0);        // g_Wog  = Wo @ Wg
    k_mat_small<<<D, 256>>>(Wv, nullptr, 1);   // g_Wvog = Wv @ g_Wog
    k_beff<<<1, 256>>>(bv, bo, Wg, bg);
    k_gate<<<B_TOK / 8, 256>>>(q, gate_out);
    k_scan<<<1, 32>>>();
    k_scatter<<<B_TOK / 256, 256>>>();
    k_gemm<1><<<dim3(D / 128, B_TOK / 128, E_EXP), 256>>>(x, W1, b1);
    k_gemm<2><<<dim3(D / 128, B_TOK / 128, E_EXP), 256>>>(nullptr, W2, b2);
    k_combine<<<(B_TOK * D / 4) / 256, 256>>>(y);
    k_loss<<<1, 32>>>(loss_out);
}